// round 1
// baseline (speedup 1.0000x reference)
#include <cuda_runtime.h>
#include <math.h>

#define S_SP 131072      // 32*64*64 spatial
#define C_IN 320
#define C_MID 160
#define NB 2
#define NTILES 1024      // S_SP / 128

// ---------------- scratch (no allocations allowed) ----------------
__device__ float d_y[(size_t)2 * NB * C_MID * S_SP];      // pre-norm conv outputs, 335.5 MB
__device__ float d_psum[2 * NB * C_MID * NTILES];         // per-tile partial sums
__device__ float d_psq [2 * NB * C_MID * NTILES];         // per-tile partial sums of squares
__device__ float d_mean[2 * NB * C_MID];
__device__ float d_rstd[2 * NB * C_MID];
__device__ float d_Wt  [2 * C_IN * C_MID];                // W transposed: [t][k][o]

// ---------------- packed fp32x2 helpers ----------------
__device__ __forceinline__ unsigned long long fma2(unsigned long long a,
                                                   unsigned long long b,
                                                   unsigned long long c) {
    unsigned long long d;
    asm("fma.rn.f32x2 %0, %1, %2, %3;" : "=l"(d) : "l"(a), "l"(b), "l"(c));
    return d;
}
__device__ __forceinline__ unsigned long long pack2(float v) {
    unsigned int u = __float_as_uint(v);
    return (unsigned long long)u | ((unsigned long long)u << 32);
}
__device__ __forceinline__ float lo32(unsigned long long p) { return __uint_as_float((unsigned int)p); }
__device__ __forceinline__ float hi32(unsigned long long p) { return __uint_as_float((unsigned int)(p >> 32)); }

__device__ __forceinline__ float elu1(float v) { return v > 0.0f ? v : expm1f(v); }

// ---------------- pass 0: transpose W into [k][o] ----------------
__global__ void transpose_w_kernel(const float* __restrict__ Wg,
                                   const float* __restrict__ Wx) {
    int t = blockIdx.x;
    const float* W = t ? Wx : Wg;
    for (int idx = threadIdx.x; idx < C_IN * C_MID; idx += blockDim.x) {
        int k = idx / C_MID;
        int o = idx % C_MID;
        d_Wt[t * C_IN * C_MID + idx] = W[o * C_IN + k];
    }
}

// ---------------- pass 1: conv1x1 (GEMM) + bias + per-tile stats ----------------
// Grid: (1024 tiles, n=2, tensor=2), 256 threads.
// CTA tile: 160 channels x 128 spatial. Thread: 20 channels x 4 spatial,
// accumulated as f32x2 pairs (40 packed accumulators).
__global__ void __launch_bounds__(256, 1)
gemm_stats_kernel(const float* __restrict__ g, const float* __restrict__ x,
                  const float* __restrict__ bg, const float* __restrict__ bx) {
    const int tile = blockIdx.x;
    const int n    = blockIdx.y;
    const int t    = blockIdx.z;

    const float* in   = t ? x : g;
    const float* bias = t ? bx : bg;
    const float* Wtb  = d_Wt + t * C_IN * C_MID;

    const int s0  = tile * 128;
    const int tid = threadIdx.x;
    const int cx  = tid >> 5;   // 0..7  -> channels [cx*20, cx*20+20)
    const int sx  = tid & 31;   // 0..31 -> spatial  [sx*4,  sx*4+4)

    __shared__ __align__(16) unsigned long long sW[8 * C_MID]; // W pairs {w,w}, [kk][o]
    __shared__ __align__(16) float sB[8 * 128];                // input tile [kk][s]

    unsigned long long acc[40];
#pragma unroll
    for (int i = 0; i < 20; i++) {
        unsigned long long b = pack2(bias[cx * 20 + i]);
        acc[2 * i] = b; acc[2 * i + 1] = b;
    }

    const float* inb = in + ((size_t)n * C_IN) * S_SP + s0;

    for (int k0 = 0; k0 < C_IN; k0 += 8) {
        // stage W chunk: rows k0..k0+7, all 160 channels, duplicated into pairs
        for (int idx = tid; idx < 8 * C_MID; idx += 256)
            sW[idx] = pack2(Wtb[k0 * C_MID + idx]);
        // stage input chunk: 8 k-rows x 128 spatial
        {
            int kk = tid >> 5;
            int c4 = (tid & 31) * 4;
            float4 v = *(const float4*)(inb + (size_t)(k0 + kk) * S_SP + c4);
            *(float4*)&sB[kk * 128 + c4] = v;
        }
        __syncthreads();
#pragma unroll
        for (int kk = 0; kk < 8; kk++) {
            ulonglong2 g2 = *(const ulonglong2*)&sB[kk * 128 + sx * 4];
            const ulonglong2* wr = (const ulonglong2*)&sW[kk * C_MID + cx * 20];
#pragma unroll
            for (int i = 0; i < 10; i++) {
                ulonglong2 w = wr[i];
                acc[4 * i + 0] = fma2(w.x, g2.x, acc[4 * i + 0]);
                acc[4 * i + 1] = fma2(w.x, g2.y, acc[4 * i + 1]);
                acc[4 * i + 2] = fma2(w.y, g2.x, acc[4 * i + 2]);
                acc[4 * i + 3] = fma2(w.y, g2.y, acc[4 * i + 3]);
            }
        }
        __syncthreads();
    }

    // epilogue: store y, reduce per-channel sum/sumsq across the warp (deterministic)
    const size_t ybase = (((size_t)(t * NB + n)) * C_MID) * S_SP + s0 + sx * 4;
    const int    pbase = ((t * NB + n) * C_MID) * NTILES + tile;
#pragma unroll
    for (int i = 0; i < 20; i++) {
        int c = cx * 20 + i;
        unsigned long long a0 = acc[2 * i], a1 = acc[2 * i + 1];
        float v0 = lo32(a0), v1 = hi32(a0), v2 = lo32(a1), v3 = hi32(a1);
        *(float4*)&d_y[ybase + (size_t)c * S_SP] = make_float4(v0, v1, v2, v3);
        float ps = (v0 + v1) + (v2 + v3);
        float pq = (v0 * v0 + v1 * v1) + (v2 * v2 + v3 * v3);
#pragma unroll
        for (int off = 16; off; off >>= 1) {
            ps += __shfl_xor_sync(0xffffffffu, ps, off);
            pq += __shfl_xor_sync(0xffffffffu, pq, off);
        }
        if (sx == 0) {
            d_psum[pbase + c * NTILES] = ps;
            d_psq [pbase + c * NTILES] = pq;
        }
    }
}

// ---------------- pass 2: finalize mean / rstd ----------------
__global__ void finalize_stats_kernel() {
    const int c = blockIdx.x, n = blockIdx.y, t = blockIdx.z;
    const int base = ((t * NB + n) * C_MID + c) * NTILES;
    __shared__ float s1[256], s2[256];
    float a = 0.0f, b = 0.0f;
    for (int i = threadIdx.x; i < NTILES; i += 256) {
        a += d_psum[base + i];
        b += d_psq [base + i];
    }
    s1[threadIdx.x] = a; s2[threadIdx.x] = b;
    __syncthreads();
    for (int st = 128; st; st >>= 1) {
        if (threadIdx.x < st) {
            s1[threadIdx.x] += s1[threadIdx.x + st];
            s2[threadIdx.x] += s2[threadIdx.x + st];
        }
        __syncthreads();
    }
    if (threadIdx.x == 0) {
        const float inv = 1.0f / (float)S_SP;
        float mean = s1[0] * inv;
        float var  = s2[0] * inv - mean * mean;
        d_mean[(t * NB + n) * C_MID + c] = mean;
        d_rstd[(t * NB + n) * C_MID + c] = rsqrtf(var + 1e-5f);
    }
}

// ---------------- pass 3: norm + elu + psi + broadcast multiply ----------------
// Grid: (S/1024, n=2), 256 threads; thread handles 4 spatial positions.
__global__ void __launch_bounds__(256)
psi_mul_kernel(const float* __restrict__ x, const float* __restrict__ Wpsi,
               const float* __restrict__ bpsi, float* __restrict__ out) {
    const int n = blockIdx.y;
    const int s = (blockIdx.x * 256 + threadIdx.x) * 4;

    __shared__ float sWp[C_MID], sMg[C_MID], sRg[C_MID], sMx[C_MID], sRx[C_MID];
    if (threadIdx.x < C_MID) {
        int c = threadIdx.x;
        sWp[c] = Wpsi[c];
        sMg[c] = d_mean[(0 * NB + n) * C_MID + c];
        sRg[c] = d_rstd[(0 * NB + n) * C_MID + c];
        sMx[c] = d_mean[(1 * NB + n) * C_MID + c];
        sRx[c] = d_rstd[(1 * NB + n) * C_MID + c];
    }
    __syncthreads();

    const float b0 = bpsi[0];
    float z0 = b0, z1 = b0, z2 = b0, z3 = b0;

    const size_t gb = ((size_t)(0 * NB + n) * C_MID) * S_SP + s;
    const size_t xb = ((size_t)(1 * NB + n) * C_MID) * S_SP + s;
#pragma unroll 4
    for (int c = 0; c < C_MID; c++) {
        float4 yg = *(const float4*)&d_y[gb + (size_t)c * S_SP];
        float4 yx = *(const float4*)&d_y[xb + (size_t)c * S_SP];
        float mg = sMg[c], rg = sRg[c], mx = sMx[c], rx = sRx[c], wp = sWp[c];
        float a0 = elu1((yg.x - mg) * rg) + elu1((yx.x - mx) * rx);
        float a1 = elu1((yg.y - mg) * rg) + elu1((yx.y - mx) * rx);
        float a2 = elu1((yg.z - mg) * rg) + elu1((yx.z - mx) * rx);
        float a3 = elu1((yg.w - mg) * rg) + elu1((yx.w - mx) * rx);
        z0 = fmaf(wp, a0, z0);
        z1 = fmaf(wp, a1, z1);
        z2 = fmaf(wp, a2, z2);
        z3 = fmaf(wp, a3, z3);
    }
    const float p0 = 1.0f / (1.0f + expf(-z0));
    const float p1 = 1.0f / (1.0f + expf(-z1));
    const float p2 = 1.0f / (1.0f + expf(-z2));
    const float p3 = 1.0f / (1.0f + expf(-z3));

    const float* xin = x   + ((size_t)n * C_IN) * S_SP + s;
    float*       ob  = out + ((size_t)n * C_IN) * S_SP + s;
#pragma unroll 4
    for (int c = 0; c < C_IN; c++) {
        float4 xv = *(const float4*)(xin + (size_t)c * S_SP);
        xv.x *= p0; xv.y *= p1; xv.z *= p2; xv.w *= p3;
        *(float4*)(ob + (size_t)c * S_SP) = xv;
    }
}

// ---------------- launch ----------------
extern "C" void kernel_launch(void* const* d_in, const int* in_sizes, int n_in,
                              void* d_out, int out_size) {
    const float* g    = (const float*)d_in[0];
    const float* x    = (const float*)d_in[1];
    const float* Wg   = (const float*)d_in[2];
    const float* bg   = (const float*)d_in[3];
    const float* Wx   = (const float*)d_in[4];
    const float* bx   = (const float*)d_in[5];
    const float* Wpsi = (const float*)d_in[6];
    const float* bpsi = (const float*)d_in[7];
    float* out = (float*)d_out;

    transpose_w_kernel<<<2, 256>>>(Wg, Wx);
    gemm_stats_kernel<<<dim3(NTILES, NB, 2), 256>>>(g, x, bg, bx);
    finalize_stats_kernel<<<dim3(C_MID, NB, 2), 256>>>();
    psi_mul_kernel<<<dim3(S_SP / 1024, NB), 256>>>(x, Wpsi, bpsi, out);
}

// round 5
// speedup vs baseline: 4.0633x; 4.0633x over previous
#include <cuda_runtime.h>
#include <math.h>
#include <stdint.h>

#define S_SP 131072      // 32*64*64
#define C_IN 320
#define C_MID 160
#define NB 2
#define TN 128           // spatial tile per CTA
#define NT (S_SP / TN)   // 1024 tiles per (n,t)
#define NPT (NT * 2)     // stat partials per channel (2 warp-halves per tile)
#define KC 32
#define NCH (C_IN / KC)  // 10

// ---------------- scratch ----------------
__device__ float d_y[(size_t)2 * NB * C_MID * S_SP];   // pre-norm conv outputs (335MB)
__device__ float d_psum[2 * NB * C_MID * NPT];
__device__ float d_psq [2 * NB * C_MID * NPT];
__device__ float d_mean[2 * NB * C_MID];
__device__ float d_rstd[2 * NB * C_MID];

// smem layout (words): A[160][36 pad] then B[32][132 pad], double buffered
#define SA 36
#define SB 132
#define A_WORDS (C_MID * SA)              // 5760
#define B_WORDS (KC * SB)                 // 4224
#define STG_WORDS (A_WORDS + B_WORDS)     // 9984
#define SMEM_BYTES (2 * STG_WORDS * 4)    // 79872

// ---------------- helpers ----------------
__device__ __forceinline__ uint32_t smem_u32(const void* p) {
    uint32_t a;
    asm("{ .reg .u64 t; cvta.to.shared.u64 t, %1; cvt.u32.u64 %0, t; }" : "=r"(a) : "l"(p));
    return a;
}
#define CP_ASYNC16(dst, src) asm volatile("cp.async.cg.shared.global [%0], [%1], 16;" :: "r"(dst), "l"(src))
#define CP_COMMIT() asm volatile("cp.async.commit_group;" ::: "memory")
#define CP_WAIT0()  asm volatile("cp.async.wait_group 0;" ::: "memory")

__device__ __forceinline__ uint32_t f2tf(float v) {
    uint32_t r; asm("cvt.rna.tf32.f32 %0, %1;" : "=r"(r) : "f"(v)); return r;
}
#define MMA(c, a, b) asm volatile( \
    "mma.sync.aligned.m16n8k8.row.col.f32.tf32.tf32.f32 " \
    "{%0,%1,%2,%3}, {%4,%5,%6,%7}, {%8,%9}, {%0,%1,%2,%3};" \
    : "+f"((c)[0]), "+f"((c)[1]), "+f"((c)[2]), "+f"((c)[3]) \
    : "r"((a)[0]), "r"((a)[1]), "r"((a)[2]), "r"((a)[3]), "r"((b)[0]), "r"((b)[1]))

__device__ __forceinline__ float elu1(float v) { return v > 0.0f ? v : expm1f(v); }

// ======================= pass 1: tf32 mma.sync GEMM + per-tile stats =======================
// grid (1024, n=2, t=2), 320 threads (10 warps: 5 M x 2 N), warp tile 32ch x 64sp.
// Bias omitted: it cancels exactly inside instance-norm.
__global__ void __launch_bounds__(320)
gemm_mma_kernel(const float* __restrict__ g, const float* __restrict__ x,
                const float* __restrict__ Wg, const float* __restrict__ Wx) {
    extern __shared__ float sm[];
    const uint32_t smb = smem_u32(sm);
    const int tid = threadIdx.x;
    const int wid = tid >> 5, lane = tid & 31;
    const int tile = blockIdx.x, n = blockIdx.y, t = blockIdx.z;
    const int s0 = tile * TN;

    const float* W   = t ? Wx : Wg;                                   // [160][320]
    const float* inb = (t ? x : g) + (size_t)n * C_IN * S_SP + s0;    // [320][S]

    const int wm = wid >> 1, wn = wid & 1;
    const int lq = lane >> 2, tig = lane & 3;

    float acc[2][8][4];
#pragma unroll
    for (int m = 0; m < 2; m++)
#pragma unroll
        for (int nf = 0; nf < 8; nf++)
#pragma unroll
            for (int j = 0; j < 4; j++) acc[m][nf][j] = 0.0f;

    // ---- staging (cp.async) ----
    auto stage = [&](int k0, int st) {
        const uint32_t ab = smb + (uint32_t)(st * STG_WORDS) * 4u;
        const uint32_t bb = ab + A_WORDS * 4u;
        // W chunk: 160 rows x 32 k -> smem [ch][k] (no transpose), 1280 float4
#pragma unroll 2
        for (int i = tid; i < 1280; i += 320) {
            int row = i >> 3, q = i & 7;
            CP_ASYNC16(ab + (uint32_t)(row * SA + q * 4) * 4u,
                       (const void*)(W + row * C_IN + k0 + q * 4));
        }
        // input chunk: 32 k-rows x 128 sp -> smem [k][sp], 1024 float4
#pragma unroll 2
        for (int i = tid; i < 1024; i += 320) {
            int k = i >> 5, p = i & 31;
            CP_ASYNC16(bb + (uint32_t)(k * SB + p * 4) * 4u,
                       (const void*)(inb + (size_t)(k0 + k) * S_SP + p * 4));
        }
    };

    stage(0, 0); CP_COMMIT();
    CP_WAIT0();
    __syncthreads();

    for (int c = 0; c < NCH; c++) {
        if (c + 1 < NCH) { stage((c + 1) * KC, (c + 1) & 1); CP_COMMIT(); }

        const float* sa = sm + (c & 1) * STG_WORDS;
        const float* sb = sa + A_WORDS;

#pragma unroll
        for (int ks = 0; ks < 4; ks++) {
            const int kk = ks * 8;
            uint32_t a[2][4];
#pragma unroll
            for (int m = 0; m < 2; m++) {
                int r0 = wm * 32 + m * 16 + lq;
                a[m][0] = f2tf(sa[r0 * SA + kk + tig]);
                a[m][1] = f2tf(sa[(r0 + 8) * SA + kk + tig]);
                a[m][2] = f2tf(sa[r0 * SA + kk + tig + 4]);
                a[m][3] = f2tf(sa[(r0 + 8) * SA + kk + tig + 4]);
            }
#pragma unroll
            for (int nf = 0; nf < 8; nf++) {
                int col = wn * 64 + nf * 8 + lq;
                uint32_t b[2];
                b[0] = f2tf(sb[(kk + tig) * SB + col]);
                b[1] = f2tf(sb[(kk + 4 + tig) * SB + col]);
                MMA(acc[0][nf], a[0], b);
                MMA(acc[1][nf], a[1], b);
            }
        }

        if (c + 1 < NCH) CP_WAIT0();
        __syncthreads();
    }

    // ---- epilogue: store y (float2, sector-aligned) + per-row partial stats ----
    float rsum[4] = {0.f, 0.f, 0.f, 0.f};
    float rsq [4] = {0.f, 0.f, 0.f, 0.f};
#pragma unroll
    for (int m = 0; m < 2; m++) {
        const int r0 = wm * 32 + m * 16 + lq;
        const size_t base = (size_t)((t * NB + n) * C_MID) * S_SP + s0 + wn * 64 + 2 * tig;
        float* y0 = d_y + base + (size_t)r0 * S_SP;
        float* y1 = d_y + base + (size_t)(r0 + 8) * S_SP;
#pragma unroll
        for (int nf = 0; nf < 8; nf++) {
            float v0 = acc[m][nf][0], v1 = acc[m][nf][1];
            float v2 = acc[m][nf][2], v3 = acc[m][nf][3];
            *(float2*)(y0 + nf * 8) = make_float2(v0, v1);
            *(float2*)(y1 + nf * 8) = make_float2(v2, v3);
            rsum[2 * m]     += v0 + v1;
            rsq [2 * m]     += v0 * v0 + v1 * v1;
            rsum[2 * m + 1] += v2 + v3;
            rsq [2 * m + 1] += v2 * v2 + v3 * v3;
        }
    }
#pragma unroll
    for (int j = 0; j < 4; j++) {
        rsum[j] += __shfl_xor_sync(0xffffffffu, rsum[j], 1);
        rsum[j] += __shfl_xor_sync(0xffffffffu, rsum[j], 2);
        rsq [j] += __shfl_xor_sync(0xffffffffu, rsq [j], 1);
        rsq [j] += __shfl_xor_sync(0xffffffffu, rsq [j], 2);
    }
    if (tig == 0) {
#pragma unroll
        for (int j = 0; j < 4; j++) {
            int ch = wm * 32 + (j >> 1) * 16 + (j & 1) * 8 + lq;
            int idx = ((t * NB + n) * C_MID + ch) * NPT + tile * 2 + wn;
            d_psum[idx] = rsum[j];
            d_psq [idx] = rsq [j];
        }
    }
}

// ======================= pass 2: finalize mean / rstd =======================
__global__ void finalize_stats_kernel() {
    const int c = blockIdx.x, n = blockIdx.y, t = blockIdx.z;
    const int base = ((t * NB + n) * C_MID + c) * NPT;
    __shared__ float s1[256], s2[256];
    float a = 0.f, b = 0.f;
    for (int i = threadIdx.x; i < NPT; i += 256) { a += d_psum[base + i]; b += d_psq[base + i]; }
    s1[threadIdx.x] = a; s2[threadIdx.x] = b;
    __syncthreads();
    for (int st = 128; st; st >>= 1) {
        if (threadIdx.x < st) { s1[threadIdx.x] += s1[threadIdx.x + st]; s2[threadIdx.x] += s2[threadIdx.x + st]; }
        __syncthreads();
    }
    if (threadIdx.x == 0) {
        const float inv = 1.0f / (float)S_SP;
        float mean = s1[0] * inv;
        float var  = s2[0] * inv - mean * mean;
        d_mean[(t * NB + n) * C_MID + c] = mean;
        d_rstd[(t * NB + n) * C_MID + c] = rsqrtf(var + 1e-5f);
    }
}

// ======================= pass 3: norm + elu + psi + multiply =======================
// grid (S_SP/512, n=2), 256 threads, 2 spatial/thread.
__global__ void __launch_bounds__(256)
psi_mul_kernel(const float* __restrict__ x, const float* __restrict__ Wpsi,
               const float* __restrict__ bpsi, float* __restrict__ out) {
    const int n = blockIdx.y;
    const int s = (blockIdx.x * 256 + threadIdx.x) * 2;

    __shared__ float sWp[C_MID], sMg[C_MID], sRg[C_MID], sMx[C_MID], sRx[C_MID];
    if (threadIdx.x < C_MID) {
        int c = threadIdx.x;
        sWp[c] = Wpsi[c];
        sMg[c] = d_mean[(0 * NB + n) * C_MID + c];
        sRg[c] = d_rstd[(0 * NB + n) * C_MID + c];
        sMx[c] = d_mean[(1 * NB + n) * C_MID + c];
        sRx[c] = d_rstd[(1 * NB + n) * C_MID + c];
    }
    __syncthreads();

    const float b0 = bpsi[0];
    float z0 = b0, z1 = b0;
    const size_t gb = ((size_t)(0 * NB + n) * C_MID) * S_SP + s;
    const size_t xb = ((size_t)(1 * NB + n) * C_MID) * S_SP + s;
#pragma unroll 4
    for (int c = 0; c < C_MID; c++) {
        float2 yg = *(const float2*)&d_y[gb + (size_t)c * S_SP];
        float2 yx = *(const float2*)&d_y[xb + (size_t)c * S_SP];
        float mg = sMg[c], rg = sRg[c], mx = sMx[c], rx = sRx[c], wp = sWp[c];
        z0 = fmaf(wp, elu1((yg.x - mg) * rg) + elu1((yx.x - mx) * rx), z0);
        z1 = fmaf(wp, elu1((yg.y - mg) * rg) + elu1((yx.y - mx) * rx), z1);
    }
    const float p0 = 1.0f / (1.0f + expf(-z0));
    const float p1 = 1.0f / (1.0f + expf(-z1));

    const float* xin = x   + ((size_t)n * C_IN) * S_SP + s;
    float*       ob  = out + ((size_t)n * C_IN) * S_SP + s;
#pragma unroll 4
    for (int c = 0; c < C_IN; c++) {
        float2 xv = *(const float2*)(xin + (size_t)c * S_SP);
        xv.x *= p0; xv.y *= p1;
        *(float2*)(ob + (size_t)c * S_SP) = xv;
    }
}

// ======================= launch =======================
extern "C" void kernel_launch(void* const* d_in, const int* in_sizes, int n_in,
                              void* d_out, int out_size) {
    const float* g    = (const float*)d_in[0];
    const float* x    = (const float*)d_in[1];
    const float* Wg   = (const float*)d_in[2];
    const float* Wx   = (const float*)d_in[4];
    const float* Wpsi = (const float*)d_in[6];
    const float* bpsi = (const float*)d_in[7];
    float* out = (float*)d_out;

    cudaFuncSetAttribute(gemm_mma_kernel, cudaFuncAttributeMaxDynamicSharedMemorySize, SMEM_BYTES);

    gemm_mma_kernel<<<dim3(NT, NB, 2), 320, SMEM_BYTES>>>(g, x, Wg, Wx);
    finalize_stats_kernel<<<dim3(C_MID, NB, 2), 256>>>();
    psi_mul_kernel<<<dim3(S_SP / 512, NB), 256>>>(x, Wpsi, bpsi, out);
}

// round 6
// speedup vs baseline: 4.8610x; 1.1963x over previous
#include <cuda_runtime.h>
#include <math.h>
#include <stdint.h>

#define S_SP 131072      // 32*64*64
#define C_IN 320
#define C_MID 160
#define NB 2
#define TN 128           // spatial tile per CTA
#define NT (S_SP / TN)   // 1024 tiles per (n,t)
#define NPT (NT * 2)     // stat partials per channel (2 warp-halves per tile)
#define KC 32
#define NCH (C_IN / KC)  // 10

// ---------------- scratch ----------------
__device__ float d_y[(size_t)2 * NB * C_MID * S_SP];   // pre-norm conv outputs (335MB)
__device__ float d_psum[2 * NB * C_MID * NPT];
__device__ float d_psq [2 * NB * C_MID * NPT];
__device__ float d_mean[2 * NB * C_MID];
__device__ float d_rstd[2 * NB * C_MID];

// smem layout (words): A[160][36 pad] then B[32][132 pad], double buffered
#define SA 36
#define SB 132
#define A_WORDS (C_MID * SA)              // 5760
#define B_WORDS (KC * SB)                 // 4224
#define STG_WORDS (A_WORDS + B_WORDS)     // 9984
#define SMEM_BYTES (2 * STG_WORDS * 4)    // 79872

// ---------------- helpers ----------------
__device__ __forceinline__ uint32_t smem_u32(const void* p) {
    uint32_t a;
    asm("{ .reg .u64 t; cvta.to.shared.u64 t, %1; cvt.u32.u64 %0, t; }" : "=r"(a) : "l"(p));
    return a;
}
#define CP_ASYNC16(dst, src) asm volatile("cp.async.cg.shared.global [%0], [%1], 16;" :: "r"(dst), "l"(src))
#define CP_COMMIT() asm volatile("cp.async.commit_group;" ::: "memory")
#define CP_WAIT0()  asm volatile("cp.async.wait_group 0;" ::: "memory")

// HMMA.TF32 ignores the low 13 mantissa bits: raw fp32 bit patterns are valid
// tf32 operands (truncation). No cvt needed.
#define MMA(c, a, b) asm volatile( \
    "mma.sync.aligned.m16n8k8.row.col.f32.tf32.tf32.f32 " \
    "{%0,%1,%2,%3}, {%4,%5,%6,%7}, {%8,%9}, {%0,%1,%2,%3};" \
    : "+f"((c)[0]), "+f"((c)[1]), "+f"((c)[2]), "+f"((c)[3]) \
    : "r"((a)[0]), "r"((a)[1]), "r"((a)[2]), "r"((a)[3]), "r"((b)[0]), "r"((b)[1]))

__device__ __forceinline__ float elu1(float v) { return v > 0.0f ? v : expm1f(v); }

// ======================= pass 1: tf32 mma.sync GEMM + per-tile stats =======================
// grid (1024, n=2, t=2), 320 threads (10 warps: 5 M x 2 N), warp tile 32ch x 64sp.
// Bias omitted: it cancels exactly inside instance-norm.
__global__ void __launch_bounds__(320, 2)
gemm_mma_kernel(const float* __restrict__ g, const float* __restrict__ x,
                const float* __restrict__ Wg, const float* __restrict__ Wx) {
    extern __shared__ float sm[];
    const uint32_t smb = smem_u32(sm);
    const int tid = threadIdx.x;
    const int wid = tid >> 5, lane = tid & 31;
    const int tile = blockIdx.x, n = blockIdx.y, t = blockIdx.z;
    const int s0 = tile * TN;

    const float* W   = t ? Wx : Wg;                                   // [160][320]
    const float* inb = (t ? x : g) + (size_t)n * C_IN * S_SP + s0;    // [320][S]

    const int wm = wid >> 1, wn = wid & 1;
    const int lq = lane >> 2, tig = lane & 3;

    float acc[2][8][4];
#pragma unroll
    for (int m = 0; m < 2; m++)
#pragma unroll
        for (int nf = 0; nf < 8; nf++)
#pragma unroll
            for (int j = 0; j < 4; j++) acc[m][nf][j] = 0.0f;

    // ---- staging (cp.async) ----
    auto stage = [&](int k0, int st) {
        const uint32_t ab = smb + (uint32_t)(st * STG_WORDS) * 4u;
        const uint32_t bb = ab + A_WORDS * 4u;
        // W chunk: 160 rows x 32 k -> smem [ch][k], 1280 float4
#pragma unroll 2
        for (int i = tid; i < 1280; i += 320) {
            int row = i >> 3, q = i & 7;
            CP_ASYNC16(ab + (uint32_t)(row * SA + q * 4) * 4u,
                       (const void*)(W + row * C_IN + k0 + q * 4));
        }
        // input chunk: 32 k-rows x 128 sp -> smem [k][sp], 1024 float4
#pragma unroll 2
        for (int i = tid; i < 1024; i += 320) {
            int k = i >> 5, p = i & 31;
            CP_ASYNC16(bb + (uint32_t)(k * SB + p * 4) * 4u,
                       (const void*)(inb + (size_t)(k0 + k) * S_SP + p * 4));
        }
    };

    stage(0, 0); CP_COMMIT();
    CP_WAIT0();
    __syncthreads();

    for (int c = 0; c < NCH; c++) {
        if (c + 1 < NCH) { stage((c + 1) * KC, (c + 1) & 1); CP_COMMIT(); }

        const float* sa = sm + (c & 1) * STG_WORDS;
        const float* sb = sa + A_WORDS;

#pragma unroll
        for (int ks = 0; ks < 4; ks++) {
            const int kk = ks * 8;
            uint32_t a[2][4];
#pragma unroll
            for (int m = 0; m < 2; m++) {
                int r0 = wm * 32 + m * 16 + lq;
                a[m][0] = __float_as_uint(sa[r0 * SA + kk + tig]);
                a[m][1] = __float_as_uint(sa[(r0 + 8) * SA + kk + tig]);
                a[m][2] = __float_as_uint(sa[r0 * SA + kk + tig + 4]);
                a[m][3] = __float_as_uint(sa[(r0 + 8) * SA + kk + tig + 4]);
            }
#pragma unroll
            for (int nf = 0; nf < 8; nf++) {
                int col = wn * 64 + nf * 8 + lq;
                uint32_t b[2];
                b[0] = __float_as_uint(sb[(kk + tig) * SB + col]);
                b[1] = __float_as_uint(sb[(kk + 4 + tig) * SB + col]);
                MMA(acc[0][nf], a[0], b);
                MMA(acc[1][nf], a[1], b);
            }
        }

        if (c + 1 < NCH) CP_WAIT0();
        __syncthreads();
    }

    // ---- epilogue: store y (float2, sector-aligned) + per-row partial stats ----
    float rsum[4] = {0.f, 0.f, 0.f, 0.f};
    float rsq [4] = {0.f, 0.f, 0.f, 0.f};
#pragma unroll
    for (int m = 0; m < 2; m++) {
        const int r0 = wm * 32 + m * 16 + lq;
        const size_t base = (size_t)((t * NB + n) * C_MID) * S_SP + s0 + wn * 64 + 2 * tig;
        float* y0 = d_y + base + (size_t)r0 * S_SP;
        float* y1 = d_y + base + (size_t)(r0 + 8) * S_SP;
#pragma unroll
        for (int nf = 0; nf < 8; nf++) {
            float v0 = acc[m][nf][0], v1 = acc[m][nf][1];
            float v2 = acc[m][nf][2], v3 = acc[m][nf][3];
            *(float2*)(y0 + nf * 8) = make_float2(v0, v1);
            *(float2*)(y1 + nf * 8) = make_float2(v2, v3);
            rsum[2 * m]     += v0 + v1;
            rsq [2 * m]     += v0 * v0 + v1 * v1;
            rsum[2 * m + 1] += v2 + v3;
            rsq [2 * m + 1] += v2 * v2 + v3 * v3;
        }
    }
#pragma unroll
    for (int j = 0; j < 4; j++) {
        rsum[j] += __shfl_xor_sync(0xffffffffu, rsum[j], 1);
        rsum[j] += __shfl_xor_sync(0xffffffffu, rsum[j], 2);
        rsq [j] += __shfl_xor_sync(0xffffffffu, rsq [j], 1);
        rsq [j] += __shfl_xor_sync(0xffffffffu, rsq [j], 2);
    }
    if (tig == 0) {
#pragma unroll
        for (int j = 0; j < 4; j++) {
            int ch = wm * 32 + (j >> 1) * 16 + (j & 1) * 8 + lq;
            int idx = ((t * NB + n) * C_MID + ch) * NPT + tile * 2 + wn;
            d_psum[idx] = rsum[j];
            d_psq [idx] = rsq [j];
        }
    }
}

// ======================= pass 2: finalize mean / rstd =======================
__global__ void finalize_stats_kernel() {
    const int c = blockIdx.x, n = blockIdx.y, t = blockIdx.z;
    const int base = ((t * NB + n) * C_MID + c) * NPT;
    __shared__ float s1[256], s2[256];
    float a = 0.f, b = 0.f;
    for (int i = threadIdx.x; i < NPT; i += 256) { a += d_psum[base + i]; b += d_psq[base + i]; }
    s1[threadIdx.x] = a; s2[threadIdx.x] = b;
    __syncthreads();
    for (int st = 128; st; st >>= 1) {
        if (threadIdx.x < st) { s1[threadIdx.x] += s1[threadIdx.x + st]; s2[threadIdx.x] += s2[threadIdx.x + st]; }
        __syncthreads();
    }
    if (threadIdx.x == 0) {
        const float inv = 1.0f / (float)S_SP;
        float mean = s1[0] * inv;
        float var  = s2[0] * inv - mean * mean;
        d_mean[(t * NB + n) * C_MID + c] = mean;
        d_rstd[(t * NB + n) * C_MID + c] = rsqrtf(var + 1e-5f);
    }
}

// ======================= pass 3: norm + elu + psi + multiply =======================
// grid (S_SP/256, n=2) = 1024 blocks, 256 threads, 1 spatial/thread (fully coalesced).
__global__ void __launch_bounds__(256)
psi_mul_kernel(const float* __restrict__ x, const float* __restrict__ Wpsi,
               const float* __restrict__ bpsi, float* __restrict__ out) {
    const int n = blockIdx.y;
    const int s = blockIdx.x * 256 + threadIdx.x;

    __shared__ float sWp[C_MID], sMg[C_MID], sRg[C_MID], sMx[C_MID], sRx[C_MID];
    if (threadIdx.x < C_MID) {
        int c = threadIdx.x;
        sWp[c] = Wpsi[c];
        sMg[c] = d_mean[(0 * NB + n) * C_MID + c];
        sRg[c] = d_rstd[(0 * NB + n) * C_MID + c];
        sMx[c] = d_mean[(1 * NB + n) * C_MID + c];
        sRx[c] = d_rstd[(1 * NB + n) * C_MID + c];
    }
    __syncthreads();

    float z = bpsi[0];
    const float* yg = d_y + ((size_t)(0 * NB + n) * C_MID) * S_SP + s;
    const float* yx = d_y + ((size_t)(1 * NB + n) * C_MID) * S_SP + s;
#pragma unroll 8
    for (int c = 0; c < C_MID; c++) {
        float vg = yg[(size_t)c * S_SP];
        float vx = yx[(size_t)c * S_SP];
        z = fmaf(sWp[c], elu1((vg - sMg[c]) * sRg[c]) + elu1((vx - sMx[c]) * sRx[c]), z);
    }
    const float p = 1.0f / (1.0f + expf(-z));

    const float* xin = x   + ((size_t)n * C_IN) * S_SP + s;
    float*       ob  = out + ((size_t)n * C_IN) * S_SP + s;
#pragma unroll 8
    for (int c = 0; c < C_IN; c++)
        ob[(size_t)c * S_SP] = xin[(size_t)c * S_SP] * p;
}

// ======================= launch =======================
extern "C" void kernel_launch(void* const* d_in, const int* in_sizes, int n_in,
                              void* d_out, int out_size) {
    const float* g    = (const float*)d_in[0];
    const float* x    = (const float*)d_in[1];
    const float* Wg   = (const float*)d_in[2];
    const float* Wx   = (const float*)d_in[4];
    const float* Wpsi = (const float*)d_in[6];
    const float* bpsi = (const float*)d_in[7];
    float* out = (float*)d_out;

    cudaFuncSetAttribute(gemm_mma_kernel, cudaFuncAttributeMaxDynamicSharedMemorySize, SMEM_BYTES);

    gemm_mma_kernel<<<dim3(NT, NB, 2), 320, SMEM_BYTES>>>(g, x, Wg, Wx);
    finalize_stats_kernel<<<dim3(C_MID, NB, 2), 256>>>();
    psi_mul_kernel<<<dim3(S_SP / 256, NB), 256>>>(x, Wpsi, bpsi, out);
}

// round 7
// speedup vs baseline: 5.4926x; 1.1299x over previous
#include <cuda_runtime.h>
#include <math.h>
#include <stdint.h>

#define S_SP 131072      // 32*64*64
#define C_IN 320
#define C_MID 160
#define NB 2
#define TN 128           // spatial tile per CTA
#define NT (S_SP / TN)   // 1024 tiles per (n,t)
#define NPT (NT * 2)     // stat partials per channel (2 warp-halves per tile)
#define KC 32
#define NCH (C_IN / KC)  // 10

// ---------------- scratch ----------------
__device__ float d_y[(size_t)2 * NB * C_MID * S_SP];   // pre-norm conv outputs (335MB)
__device__ float d_psum[2 * NB * C_MID * NPT];
__device__ float d_psq [2 * NB * C_MID * NPT];
__device__ float d_mean[2 * NB * C_MID];
__device__ float d_rstd[2 * NB * C_MID];

// smem layout (words): A[160][36 pad] then B[32][136 pad], double buffered
// SA=36: A-load bank = lq*4+tig  (perfect permutation, conflict-free)
// SB=136 (==8 mod 32): B-load bank = tig*8+lq (perfect permutation, conflict-free)
#define SA 36
#define SB 136
#define A_WORDS (C_MID * SA)              // 5760
#define B_WORDS (KC * SB)                 // 4352
#define STG_WORDS (A_WORDS + B_WORDS)     // 10112
#define SMEM_BYTES (2 * STG_WORDS * 4)    // 80896

// ---------------- helpers ----------------
__device__ __forceinline__ uint32_t smem_u32(const void* p) {
    uint32_t a;
    asm("{ .reg .u64 t; cvta.to.shared.u64 t, %1; cvt.u32.u64 %0, t; }" : "=r"(a) : "l"(p));
    return a;
}
#define CP_ASYNC16(dst, src) asm volatile("cp.async.cg.shared.global [%0], [%1], 16;" :: "r"(dst), "l"(src))
#define CP_COMMIT() asm volatile("cp.async.commit_group;" ::: "memory")
#define CP_WAIT0()  asm volatile("cp.async.wait_group 0;" ::: "memory")

// HMMA.TF32 ignores the low 13 mantissa bits: raw fp32 bit patterns are valid
// tf32 operands (truncation). No cvt needed.
#define MMA(c, a, b) asm volatile( \
    "mma.sync.aligned.m16n8k8.row.col.f32.tf32.tf32.f32 " \
    "{%0,%1,%2,%3}, {%4,%5,%6,%7}, {%8,%9}, {%0,%1,%2,%3};" \
    : "+f"((c)[0]), "+f"((c)[1]), "+f"((c)[2]), "+f"((c)[3]) \
    : "r"((a)[0]), "r"((a)[1]), "r"((a)[2]), "r"((a)[3]), "r"((b)[0]), "r"((b)[1]))

__device__ __forceinline__ float elu1(float v) { return v > 0.0f ? v : expm1f(v); }

// ======================= pass 1: tf32 mma.sync GEMM + per-tile stats =======================
// grid (1024, n=2, t=2), 320 threads (10 warps: 5 M x 2 N), warp tile 32ch x 64sp.
// Bias omitted: it cancels exactly inside instance-norm.
__global__ void __launch_bounds__(320, 2)
gemm_mma_kernel(const float* __restrict__ g, const float* __restrict__ x,
                const float* __restrict__ Wg, const float* __restrict__ Wx) {
    extern __shared__ float sm[];
    const uint32_t smb = smem_u32(sm);
    const int tid = threadIdx.x;
    const int wid = tid >> 5, lane = tid & 31;
    const int tile = blockIdx.x, n = blockIdx.y, t = blockIdx.z;
    const int s0 = tile * TN;

    const float* W   = t ? Wx : Wg;                                   // [160][320]
    const float* inb = (t ? x : g) + (size_t)n * C_IN * S_SP + s0;    // [320][S]

    const int wm = wid >> 1, wn = wid & 1;
    const int lq = lane >> 2, tig = lane & 3;

    float acc[2][8][4];
#pragma unroll
    for (int m = 0; m < 2; m++)
#pragma unroll
        for (int nf = 0; nf < 8; nf++)
#pragma unroll
            for (int j = 0; j < 4; j++) acc[m][nf][j] = 0.0f;

    // ---- staging (cp.async) ----
    auto stage = [&](int k0, int st) {
        const uint32_t ab = smb + (uint32_t)(st * STG_WORDS) * 4u;
        const uint32_t bb = ab + A_WORDS * 4u;
        // W chunk: 160 rows x 32 k -> smem [ch][k], 1280 float4
#pragma unroll 2
        for (int i = tid; i < 1280; i += 320) {
            int row = i >> 3, q = i & 7;
            CP_ASYNC16(ab + (uint32_t)(row * SA + q * 4) * 4u,
                       (const void*)(W + row * C_IN + k0 + q * 4));
        }
        // input chunk: 32 k-rows x 128 sp -> smem [k][sp], 1024 float4
#pragma unroll 2
        for (int i = tid; i < 1024; i += 320) {
            int k = i >> 5, p = i & 31;
            CP_ASYNC16(bb + (uint32_t)(k * SB + p * 4) * 4u,
                       (const void*)(inb + (size_t)(k0 + k) * S_SP + p * 4));
        }
    };

    stage(0, 0); CP_COMMIT();
    CP_WAIT0();
    __syncthreads();

    for (int c = 0; c < NCH; c++) {
        if (c + 1 < NCH) { stage((c + 1) * KC, (c + 1) & 1); CP_COMMIT(); }

        const float* sa = sm + (c & 1) * STG_WORDS;
        const float* sb = sa + A_WORDS;

#pragma unroll
        for (int ks = 0; ks < 4; ks++) {
            const int kk = ks * 8;
            uint32_t a[2][4];
#pragma unroll
            for (int m = 0; m < 2; m++) {
                int r0 = wm * 32 + m * 16 + lq;
                a[m][0] = __float_as_uint(sa[r0 * SA + kk + tig]);
                a[m][1] = __float_as_uint(sa[(r0 + 8) * SA + kk + tig]);
                a[m][2] = __float_as_uint(sa[r0 * SA + kk + tig + 4]);
                a[m][3] = __float_as_uint(sa[(r0 + 8) * SA + kk + tig + 4]);
            }
#pragma unroll
            for (int nf = 0; nf < 8; nf++) {
                int col = wn * 64 + nf * 8 + lq;
                uint32_t b[2];
                b[0] = __float_as_uint(sb[(kk + tig) * SB + col]);
                b[1] = __float_as_uint(sb[(kk + 4 + tig) * SB + col]);
                MMA(acc[0][nf], a[0], b);
                MMA(acc[1][nf], a[1], b);
            }
        }

        if (c + 1 < NCH) CP_WAIT0();
        __syncthreads();
    }

    // ---- epilogue: store y (float2, sector-aligned) + per-row partial stats ----
    float rsum[4] = {0.f, 0.f, 0.f, 0.f};
    float rsq [4] = {0.f, 0.f, 0.f, 0.f};
#pragma unroll
    for (int m = 0; m < 2; m++) {
        const int r0 = wm * 32 + m * 16 + lq;
        const size_t base = (size_t)((t * NB + n) * C_MID) * S_SP + s0 + wn * 64 + 2 * tig;
        float* y0 = d_y + base + (size_t)r0 * S_SP;
        float* y1 = d_y + base + (size_t)(r0 + 8) * S_SP;
#pragma unroll
        for (int nf = 0; nf < 8; nf++) {
            float v0 = acc[m][nf][0], v1 = acc[m][nf][1];
            float v2 = acc[m][nf][2], v3 = acc[m][nf][3];
            *(float2*)(y0 + nf * 8) = make_float2(v0, v1);
            *(float2*)(y1 + nf * 8) = make_float2(v2, v3);
            rsum[2 * m]     += v0 + v1;
            rsq [2 * m]     += v0 * v0 + v1 * v1;
            rsum[2 * m + 1] += v2 + v3;
            rsq [2 * m + 1] += v2 * v2 + v3 * v3;
        }
    }
#pragma unroll
    for (int j = 0; j < 4; j++) {
        rsum[j] += __shfl_xor_sync(0xffffffffu, rsum[j], 1);
        rsum[j] += __shfl_xor_sync(0xffffffffu, rsum[j], 2);
        rsq [j] += __shfl_xor_sync(0xffffffffu, rsq [j], 1);
        rsq [j] += __shfl_xor_sync(0xffffffffu, rsq [j], 2);
    }
    if (tig == 0) {
#pragma unroll
        for (int j = 0; j < 4; j++) {
            int ch = wm * 32 + (j >> 1) * 16 + (j & 1) * 8 + lq;
            int idx = ((t * NB + n) * C_MID + ch) * NPT + tile * 2 + wn;
            d_psum[idx] = rsum[j];
            d_psq [idx] = rsq [j];
        }
    }
}

// ======================= pass 2: finalize mean / rstd =======================
__global__ void finalize_stats_kernel() {
    const int c = blockIdx.x, n = blockIdx.y, t = blockIdx.z;
    const int base = ((t * NB + n) * C_MID + c) * NPT;
    __shared__ float s1[256], s2[256];
    float a = 0.f, b = 0.f;
    for (int i = threadIdx.x; i < NPT; i += 256) { a += d_psum[base + i]; b += d_psq[base + i]; }
    s1[threadIdx.x] = a; s2[threadIdx.x] = b;
    __syncthreads();
    for (int st = 128; st; st >>= 1) {
        if (threadIdx.x < st) { s1[threadIdx.x] += s1[threadIdx.x + st]; s2[threadIdx.x] += s2[threadIdx.x + st]; }
        __syncthreads();
    }
    if (threadIdx.x == 0) {
        const float inv = 1.0f / (float)S_SP;
        float mean = s1[0] * inv;
        float var  = s2[0] * inv - mean * mean;
        d_mean[(t * NB + n) * C_MID + c] = mean;
        d_rstd[(t * NB + n) * C_MID + c] = rsqrtf(var + 1e-5f);
    }
}

// ======================= pass 3: norm + elu + psi + multiply =======================
// grid (S_SP/512, n=2), 256 threads, 2 spatial/thread (float2 — measured faster than scalar).
__global__ void __launch_bounds__(256)
psi_mul_kernel(const float* __restrict__ x, const float* __restrict__ Wpsi,
               const float* __restrict__ bpsi, float* __restrict__ out) {
    const int n = blockIdx.y;
    const int s = (blockIdx.x * 256 + threadIdx.x) * 2;

    __shared__ float sWp[C_MID], sMg[C_MID], sRg[C_MID], sMx[C_MID], sRx[C_MID];
    if (threadIdx.x < C_MID) {
        int c = threadIdx.x;
        sWp[c] = Wpsi[c];
        sMg[c] = d_mean[(0 * NB + n) * C_MID + c];
        sRg[c] = d_rstd[(0 * NB + n) * C_MID + c];
        sMx[c] = d_mean[(1 * NB + n) * C_MID + c];
        sRx[c] = d_rstd[(1 * NB + n) * C_MID + c];
    }
    __syncthreads();

    const float b0 = bpsi[0];
    float z0 = b0, z1 = b0;
    const size_t gb = ((size_t)(0 * NB + n) * C_MID) * S_SP + s;
    const size_t xb = ((size_t)(1 * NB + n) * C_MID) * S_SP + s;
#pragma unroll 8
    for (int c = 0; c < C_MID; c++) {
        float2 yg = *(const float2*)&d_y[gb + (size_t)c * S_SP];
        float2 yx = *(const float2*)&d_y[xb + (size_t)c * S_SP];
        float mg = sMg[c], rg = sRg[c], mx = sMx[c], rx = sRx[c], wp = sWp[c];
        z0 = fmaf(wp, elu1((yg.x - mg) * rg) + elu1((yx.x - mx) * rx), z0);
        z1 = fmaf(wp, elu1((yg.y - mg) * rg) + elu1((yx.y - mx) * rx), z1);
    }
    const float p0 = 1.0f / (1.0f + expf(-z0));
    const float p1 = 1.0f / (1.0f + expf(-z1));

    const float* xin = x   + ((size_t)n * C_IN) * S_SP + s;
    float*       ob  = out + ((size_t)n * C_IN) * S_SP + s;
#pragma unroll 8
    for (int c = 0; c < C_IN; c++) {
        float2 xv = *(const float2*)(xin + (size_t)c * S_SP);
        xv.x *= p0; xv.y *= p1;
        *(float2*)(ob + (size_t)c * S_SP) = xv;
    }
}

// ======================= launch =======================
extern "C" void kernel_launch(void* const* d_in, const int* in_sizes, int n_in,
                              void* d_out, int out_size) {
    const float* g    = (const float*)d_in[0];
    const float* x    = (const float*)d_in[1];
    const float* Wg   = (const float*)d_in[2];
    const float* Wx   = (const float*)d_in[4];
    const float* Wpsi = (const float*)d_in[6];
    const float* bpsi = (const float*)d_in[7];
    float* out = (float*)d_out;

    cudaFuncSetAttribute(gemm_mma_kernel, cudaFuncAttributeMaxDynamicSharedMemorySize, SMEM_BYTES);

    gemm_mma_kernel<<<dim3(NT, NB, 2), 320, SMEM_BYTES>>>(g, x, Wg, Wx);
    finalize_stats_kernel<<<dim3(C_MID, NB, 2), 256>>>();
    psi_mul_kernel<<<dim3(S_SP / 512, NB), 256>>>(x, Wpsi, bpsi, out);
}